// round 16
// baseline (speedup 1.0000x reference)
#include <cuda_runtime.h>
#include <cuda_fp16.h>
#include <math.h>
#include <stdint.h>

// Problem constants (fixed by the dataset)
#define B_   32
#define D_   1024
#define N_   65536
#define K_   4096
#define H_   8
#define HD_  128
#define NSPLIT 16
#define GSPLIT 4

typedef unsigned long long u64;
typedef unsigned int       u32;

// ---------------- scratch (static device globals; no allocation) -------------
__device__ u32  g_strip[1024];      // coarse histogram: top 10 bits of ck
__device__ int  g_Tst;              // threshold strip
__device__ int  g_cumAbove;
__device__ int  g_num_cand;
__device__ int  g_sel_count;
__device__ u64  g_cand[N_];
__device__ u64  g_sel_ck[K_];
__device__ int  g_sorted_idx[K_];
__device__ __half g_WkH[D_ * D_];   // W^T as fp16: [n][k]
__device__ __half g_WvH[D_ * D_];
__device__ __half g_aH[K_ * D_];    // gathered rows as fp16: [m][k]
__device__ float g_kproj[K_ * D_];
__device__ float g_vproj[K_ * D_];
__device__ float g_qproj[B_ * D_];
__device__ float g_attn[B_ * H_ * K_];
__device__ float g_ctx_part[NSPLIT * B_ * D_];
__device__ float g_ctx[B_ * D_];
__device__ float g_gpart[GSPLIT * B_ * D_];

// m16n8k16 fp16 MMA, fp32 accum (base PTX, sm_80+; no sm_103a-gated features)
__device__ __forceinline__ void mma_f16(
    float& c0, float& c1, float& c2, float& c3,
    u32 a0, u32 a1, u32 a2, u32 a3, u32 b0, u32 b1)
{
    asm volatile(
        "mma.sync.aligned.m16n8k16.row.col.f32.f16.f16.f32 "
        "{%0,%1,%2,%3}, {%4,%5,%6,%7}, {%8,%9}, {%0,%1,%2,%3};"
        : "+f"(c0), "+f"(c1), "+f"(c2), "+f"(c3)
        : "r"(a0), "r"(a1), "r"(a2), "r"(a3), "r"(b0), "r"(b1));
}

__device__ __forceinline__ u32 smem_u32(const void* p) {
    u32 a;
    asm("{ .reg .u64 t; cvta.to.shared.u64 t, %1; cvt.u32.u64 %0, t; }" : "=r"(a) : "l"(p));
    return a;
}
__device__ __forceinline__ void cp_async16(u32 dst, const void* src) {
    asm volatile("cp.async.ca.shared.global [%0], [%1], 16;" :: "r"(dst), "l"(src));
}
#define CP_COMMIT() asm volatile("cp.async.commit_group;" ::: "memory")
#define CP_WAIT1()  asm volatile("cp.async.wait_group 1;" ::: "memory")

// Composite key: (monotone(float) << 32) | (0xFFFFFFFF - index)
// Descending composite order == (value desc, index asc) == jax.lax.top_k order.
__device__ __forceinline__ u64 make_ck(float f, int i) {
    u32 x = __float_as_uint(f);
    u32 t = (x & 0x80000000u) ? ~x : (x | 0x80000000u);
    return ((u64)t << 32) | (u32)(0xFFFFFFFFu - (u32)i);
}

// ---------------- selection (strip-only: 1024 coarse bins) ----------------
__global__ void k_zero() {
    int gtid = blockIdx.x * blockDim.x + threadIdx.x;   // 1024 total
    g_strip[gtid] = 0;
    if (gtid == 0) { g_num_cand = 0; g_sel_count = 0; }
}

__global__ void k_hist_strip(const float* __restrict__ prio) {
    int stride = gridDim.x * blockDim.x;
    for (int i = blockIdx.x * blockDim.x + threadIdx.x; i < N_; i += stride) {
        u64 ck = make_ck(prio[i], i);
        atomicAdd(&g_strip[(u32)(ck >> 54)], 1u);
    }
}

// Single CTA, 1024 threads: find threshold strip via scan + boundary pick.
__global__ void k_findbin() {
    __shared__ u32 strip[1024];
    int t = threadIdx.x;

    strip[t] = g_strip[1023 - t];   // descending strip order
    __syncthreads();

    for (int off = 1; off < 1024; off <<= 1) {
        u32 v = strip[t];
        u32 a = (t >= off) ? strip[t - off] : 0u;
        __syncthreads();
        strip[t] = v + a;
        __syncthreads();
    }

    u32 inc  = strip[t];
    u32 prev = (t == 0) ? 0u : strip[t - 1];
    if (inc >= (u32)K_ && prev < (u32)K_) {
        g_Tst = 1023 - t;
        g_cumAbove = (int)prev;
    }
}

__global__ void k_compact(const float* __restrict__ prio) {
    int Tst = g_Tst;
    int stride = gridDim.x * blockDim.x;
    for (int i = blockIdx.x * blockDim.x + threadIdx.x; i < N_; i += stride) {
        u64 ck = make_ck(prio[i], i);
        int st = (int)(u32)(ck >> 54);
        if (st > Tst) {
            int p = atomicAdd(&g_sel_count, 1);
            g_sel_ck[p] = ck;
        } else if (st == Tst) {
            int p = atomicAdd(&g_num_cand, 1);
            g_cand[p] = ck;
        }
    }
}

// Single CTA: refine the low 54 bits among the candidate set
// (one 6-bit pass at shift 48, then six 8-bit passes at 40..0).
__global__ void k_selfin54() {
    __shared__ u64 sc[4096];
    __shared__ u32 hist[256];
    __shared__ u64 s_pref;
    __shared__ int s_R;
    int t = threadIdx.x;  // 256
    int nc = g_num_cand;
    bool inSm = (nc <= 4096);
    if (inSm) for (int i = t; i < nc; i += 256) sc[i] = g_cand[i];
    if (t == 0) {
        s_pref = ((u64)(u32)g_Tst) << 54;
        s_R = K_ - g_cumAbove;
    }
    __syncthreads();
#pragma unroll
    for (int pass = 0; pass < 7; pass++) {
        int shift = (pass == 0) ? 48 : (48 - 8 * pass);
        u32 fmask = (pass == 0) ? 0x3Fu : 0xFFu;
        int width = (pass == 0) ? 6 : 8;
        hist[t] = 0;
        __syncthreads();
        u64 pref  = s_pref;
        u64 hmask = (~0ULL) << (shift + width);
        for (int i = t; i < nc; i += 256) {
            u64 ck = inSm ? sc[i] : g_cand[i];
            if ((ck & hmask) == pref)
                atomicAdd(&hist[(u32)(ck >> shift) & fmask], 1u);
        }
        __syncthreads();
        if (t == 0) {
            int R = s_R, cum = 0, b = 0;
            for (int bb = (int)fmask; bb >= 0; bb--) {
                if (cum + (int)hist[bb] >= R) { b = bb; break; }
                cum += (int)hist[bb];
            }
            s_pref = pref | (((u64)(u32)b) << shift);
            s_R = R - cum;
        }
        __syncthreads();
    }
    u64 T = s_pref;
    for (int i = t; i < nc; i += 256) {
        u64 ck = inSm ? sc[i] : g_cand[i];
        if (ck >= T) {
            int p = atomicAdd(&g_sel_count, 1);
            g_sel_ck[p] = ck;
        }
    }
}

// Rank sort: one warp per selected element, pairwise count of larger keys.
__global__ void k_rank() {
    __shared__ u64 s_ck[K_];  // 32 KB
    int t = threadIdx.x;
    for (int i = t; i < K_; i += blockDim.x) s_ck[i] = g_sel_ck[i];
    __syncthreads();
    int warp = t >> 5, lane = t & 31;
    int i = blockIdx.x * 8 + warp;
    u64 my = s_ck[i];
    int cnt = 0;
    for (int j = lane; j < K_; j += 32)
        cnt += (s_ck[j] > my) ? 1 : 0;
#pragma unroll
    for (int o = 16; o > 0; o >>= 1) cnt += __shfl_down_sync(0xFFFFFFFFu, cnt, o);
    if (lane == 0)
        g_sorted_idx[cnt] = (int)(0xFFFFFFFFu - (u32)(my & 0xFFFFFFFFull));
}

// ---------------- pre-convert W: fp16 transpose WT[n][k] ----------------
__global__ void k_cvtW(const float* __restrict__ Wk, const float* __restrict__ Wv) {
    __shared__ float tile[32][33];
    const float* W = blockIdx.z ? Wv : Wk;
    __half* WT     = blockIdx.z ? g_WvH : g_WkH;
    int n  = blockIdx.x * 32 + threadIdx.x;
    int k0 = blockIdx.y * 32;
    for (int i = threadIdx.y; i < 32; i += 8)
        tile[i][threadIdx.x] = W[(size_t)(k0 + i) * D_ + n];
    __syncthreads();
    int k   = k0 + threadIdx.x;
    int nn0 = blockIdx.x * 32;
    for (int i = threadIdx.y; i < 32; i += 8)
        WT[(size_t)(nn0 + i) * D_ + k] = __float2half_rn(tile[threadIdx.x][i]);
}

// ---------------- pre-gather A rows as fp16 ----------------
__global__ void k_gatherA(const float* __restrict__ buffer) {
    int row = blockIdx.x;                 // 4096
    const float4* src = (const float4*)(buffer + (size_t)g_sorted_idx[row] * D_);
    uint2* dst = (uint2*)(g_aH + (size_t)row * D_);
    int t = threadIdx.x;                  // 256
    float4 v = src[t];
    __half2 h0 = __floats2half2_rn(v.x, v.y);
    __half2 h1 = __floats2half2_rn(v.z, v.w);
    dst[t] = make_uint2(*(u32*)&h0, *(u32*)&h1);
}

// ============ K/V projection: fp16 m16n8k16 + cp.async 3-stage pipeline ======
// CTA tile 128x128, 8 warps, warp tile 64x32 (4x4 frags of 16x8), K chunks of 32.
// z passed as a kernel arg (K-half / V-half launched concurrently for overlap).
#define KV_CH 32
#define KV_NCH (D_ / KV_CH)            // 32
#define KV_ROW_U32 28
#define KV_STAGE_U32 (2 * 128 * KV_ROW_U32)  // 7168 u32 = 28672 B
#define KV_STAGE_B   (KV_STAGE_U32 * 4)
#define KV_SMEM_BYTES (3 * KV_STAGE_B)       // 86016

__global__ void __launch_bounds__(256, 2)
k_kvproj_mma(const float* __restrict__ bias, int z)
{
    extern __shared__ u32 dsm[];
    u32 sbase = smem_u32(dsm);

    const __half* WH  = z ? g_WvH : g_WkH;
    float* out        = z ? g_vproj : g_kproj;
    int m0 = blockIdx.y * 128;
    int n0 = blockIdx.x * 128;

    int t    = threadIdx.x;
    int lane = t & 31, wid = t >> 5;
    int grp  = lane >> 2, qid = lane & 3;
    int wm   = (wid >> 2) * 64;   // 0 / 64
    int wn   = (wid & 3) * 32;    // 0 / 32 / 64 / 96

    int row = t >> 1, hf = (t & 1) * 32;
    const char* aSrc = (const char*)(g_aH + (size_t)(m0 + row) * D_) + hf;
    const char* bSrc = (const char*)(WH   + (size_t)(n0 + row) * D_) + hf;
    u32 dstA = sbase + (u32)(row * 112 + hf);
    u32 dstB = dstA + (u32)(128 * 112);

#define KV_ISSUE(c) do { \
    u32 _so = (u32)(((c) % 3) * KV_STAGE_B); \
    const char* _as = aSrc + (size_t)(c) * 64; \
    const char* _bs = bSrc + (size_t)(c) * 64; \
    cp_async16(dstA + _so,      _as); \
    cp_async16(dstA + _so + 16, _as + 16); \
    cp_async16(dstB + _so,      _bs); \
    cp_async16(dstB + _so + 16, _bs + 16); \
    CP_COMMIT(); \
} while (0)

    float acc[4][4][4];
#pragma unroll
    for (int i = 0; i < 4; i++)
#pragma unroll
        for (int j = 0; j < 4; j++)
#pragma unroll
            for (int q = 0; q < 4; q++) acc[i][j][q] = 0.0f;

    KV_ISSUE(0);
    KV_ISSUE(1);

    for (int c = 0; c < KV_NCH; c++) {
        CP_WAIT1();
        __syncthreads();
        if (c + 2 < KV_NCH) KV_ISSUE(c + 2);

        const u32* As = dsm + (c % 3) * KV_STAGE_U32;
        const u32* Bs = As + 128 * KV_ROW_U32;
#pragma unroll
        for (int kk = 0; kk < 2; kk++) {
            int kb = kk * 8;
            u32 af[4][4], bf[4][2];
#pragma unroll
            for (int mf = 0; mf < 4; mf++) {
                int r = wm + mf * 16 + grp;
                af[mf][0] = As[r * KV_ROW_U32 + kb + qid];
                af[mf][1] = As[(r + 8) * KV_ROW_U32 + kb + qid];
                af[mf][2] = As[r * KV_ROW_U32 + kb + qid + 4];
                af[mf][3] = As[(r + 8) * KV_ROW_U32 + kb + qid + 4];
            }
#pragma unroll
            for (int nf = 0; nf < 4; nf++) {
                int n = wn + nf * 8 + grp;
                bf[nf][0] = Bs[n * KV_ROW_U32 + kb + qid];
                bf[nf][1] = Bs[n * KV_ROW_U32 + kb + qid + 4];
            }
#pragma unroll
            for (int mf = 0; mf < 4; mf++)
#pragma unroll
                for (int nf = 0; nf < 4; nf++)
                    mma_f16(acc[mf][nf][0], acc[mf][nf][1], acc[mf][nf][2], acc[mf][nf][3],
                            af[mf][0], af[mf][1], af[mf][2], af[mf][3],
                            bf[nf][0], bf[nf][1]);
        }
    }

#pragma unroll
    for (int mf = 0; mf < 4; mf++) {
#pragma unroll
        for (int nf = 0; nf < 4; nf++) {
            int n = n0 + wn + nf * 8 + 2 * qid;
            float bv0 = bias[n], bv1 = bias[n + 1];
            int r0 = m0 + wm + mf * 16 + grp;
            float2 v0 = make_float2(acc[mf][nf][0] + bv0, acc[mf][nf][1] + bv1);
            float2 v1 = make_float2(acc[mf][nf][2] + bv0, acc[mf][nf][3] + bv1);
            *(float2*)(out + (size_t)r0 * D_ + n)       = v0;
            *(float2*)(out + (size_t)(r0 + 8) * D_ + n) = v1;
        }
    }
#undef KV_ISSUE
}

// ---------------- M=32 GEMM, split-K (q proj: mode 0, out proj: mode 1) -----
__global__ void k_gemm32s(const float* __restrict__ Aext,
                          const float* __restrict__ W, int mode)
{
    const float* A = (mode == 0) ? Aext : g_ctx;
    int n0 = blockIdx.x * 128;
    int ks = blockIdx.y * (D_ / GSPLIT);   // 256-wide K slice

    __shared__ float As[32][36];   // [k][b]
    __shared__ float Bs[32][128];  // [k][n]
    int t = threadIdx.x;
    float acc[4][4] = {};
    int rm = (t >> 5) * 4, rn = (t & 31) * 4;
    int ab = t >> 3, akq = (t & 7) * 4;

    for (int k0 = ks; k0 < ks + D_ / GSPLIT; k0 += 32) {
        float4 av = *(const float4*)(A + (size_t)ab * D_ + k0 + akq);
        As[akq+0][ab]=av.x; As[akq+1][ab]=av.y; As[akq+2][ab]=av.z; As[akq+3][ab]=av.w;
#pragma unroll
        for (int p = 0; p < 4; p++) {
            int id = t + p * 256;
            int br = id >> 5, bc = (id & 31) * 4;
            *(float4*)&Bs[br][bc] = *(const float4*)(W + (size_t)(k0 + br) * D_ + n0 + bc);
        }
        __syncthreads();
#pragma unroll
        for (int kk = 0; kk < 32; kk++) {
            float a[4], b[4];
            *(float4*)&a[0] = *(const float4*)&As[kk][rm];
            *(float4*)&b[0] = *(const float4*)&Bs[kk][rn];
#pragma unroll
            for (int i = 0; i < 4; i++)
#pragma unroll
                for (int j = 0; j < 4; j++)
                    acc[i][j] += a[i] * b[j];
        }
        __syncthreads();
    }
#pragma unroll
    for (int i = 0; i < 4; i++) {
        float* op = g_gpart + ((size_t)blockIdx.y * B_ + rm + i) * D_ + n0 + rn;
#pragma unroll
        for (int j = 0; j < 4; j++)
            op[j] = acc[i][j];
    }
}

__global__ void k_gemmred(const float* __restrict__ bias,
                          float* __restrict__ outext, int mode)
{
    float* dst = (mode == 0) ? g_qproj : outext;
    int i = blockIdx.x * blockDim.x + threadIdx.x;  // 32768
    int n = i & (D_ - 1);
    float s = bias[n];
#pragma unroll
    for (int sp = 0; sp < GSPLIT; sp++) s += g_gpart[(size_t)sp * B_ * D_ + i];
    dst[i] = s;
}

// ---------------- scores[b,h,j] = scale * q[b,h,:] . k[j,h,:] ---------------
__global__ void k_scores() {
    int j0 = blockIdx.x * 128;
    int h  = blockIdx.y;
    __shared__ float As[32][36];   // [d][b]
    __shared__ float Bs[32][132];  // [d][j]
    int t = threadIdx.x;
    float acc[4][4] = {};
    int rm = (t >> 5) * 4, rn = (t & 31) * 4;
    int ab = t >> 3, akq = (t & 7) * 4;

    for (int d0 = 0; d0 < HD_; d0 += 32) {
        float4 av = *(const float4*)(g_qproj + (size_t)ab * D_ + h * HD_ + d0 + akq);
        As[akq+0][ab]=av.x; As[akq+1][ab]=av.y; As[akq+2][ab]=av.z; As[akq+3][ab]=av.w;
#pragma unroll
        for (int p = 0; p < 4; p++) {
            int id = t + p * 256;
            int jr = id >> 3, dq = (id & 7) * 4;
            float4 bvv = *(const float4*)(g_kproj + (size_t)(j0 + jr) * D_ + h * HD_ + d0 + dq);
            Bs[dq+0][jr]=bvv.x; Bs[dq+1][jr]=bvv.y; Bs[dq+2][jr]=bvv.z; Bs[dq+3][jr]=bvv.w;
        }
        __syncthreads();
#pragma unroll
        for (int kk = 0; kk < 32; kk++) {
            float a[4], b[4];
            *(float4*)&a[0] = *(const float4*)&As[kk][rm];
            *(float4*)&b[0] = *(const float4*)&Bs[kk][rn];
#pragma unroll
            for (int i = 0; i < 4; i++)
#pragma unroll
                for (int j = 0; j < 4; j++)
                    acc[i][j] += a[i] * b[j];
        }
        __syncthreads();
    }
    const float scale = 0.08838834764831845f;  // 128^-0.5
#pragma unroll
    for (int i = 0; i < 4; i++)
#pragma unroll
        for (int j = 0; j < 4; j++)
            g_attn[((size_t)(rm + i) * H_ + h) * K_ + j0 + rn + j] = acc[i][j] * scale;
}

// ---------------- softmax over j (in place), one CTA per (b,h) row ----------
__global__ void k_softmax() {
    int row = blockIdx.x;
    float* p = g_attn + (size_t)row * K_;
    __shared__ float sd[K_];
    __shared__ float red[256];
    int t = threadIdx.x;
    float mx = -1e30f;
    for (int i = t; i < K_; i += 256) { float v = p[i]; sd[i] = v; mx = fmaxf(mx, v); }
    red[t] = mx; __syncthreads();
    for (int o = 128; o > 0; o >>= 1) { if (t < o) red[t] = fmaxf(red[t], red[t + o]); __syncthreads(); }
    mx = red[0]; __syncthreads();
    float sum = 0.0f;
    for (int i = t; i < K_; i += 256) { float e = expf(sd[i] - mx); sd[i] = e; sum += e; }
    red[t] = sum; __syncthreads();
    for (int o = 128; o > 0; o >>= 1) { if (t < o) red[t] += red[t + o]; __syncthreads(); }
    float inv = 1.0f / red[0];
    for (int i = t; i < K_; i += 256) p[i] = sd[i] * inv;
}

// ---------------- attn_avg = mean over heads -> d_out[32768:] ---------------
__global__ void k_avg(float* __restrict__ out2) {
    int idx = blockIdx.x * blockDim.x + threadIdx.x;  // 131072 total
    int b = idx >> 12, j = idx & 4095;
    float s = 0.0f;
#pragma unroll
    for (int h = 0; h < H_; h++) s += g_attn[((size_t)b * H_ + h) * K_ + j];
    out2[(size_t)b * K_ + j] = s * 0.125f;
}

// ---------------- ctx partials: attn[b,h,:] @ v[:,h,:] over j-split ---------
__global__ void k_ctxpart() {
    int h  = blockIdx.x;       // 8
    int sp = blockIdx.y;       // 16
    int jbase = sp * (K_ / NSPLIT);   // 256 j per split
    __shared__ float As[32][36];    // [j][b]
    __shared__ float Bs[32][128];   // [j][d]
    int t = threadIdx.x;
    float acc[4][4] = {};
    int rm = (t >> 5) * 4, rn = (t & 31) * 4;
    int ab = t >> 3, ajq = (t & 7) * 4;

    for (int k0 = 0; k0 < K_ / NSPLIT; k0 += 32) {
        float4 av = *(const float4*)(g_attn + ((size_t)ab * H_ + h) * K_ + jbase + k0 + ajq);
        As[ajq+0][ab]=av.x; As[ajq+1][ab]=av.y; As[ajq+2][ab]=av.z; As[ajq+3][ab]=av.w;
#pragma unroll
        for (int p = 0; p < 4; p++) {
            int id = t + p * 256;
            int jr = id >> 5, dc = (id & 31) * 4;
            *(float4*)&Bs[jr][dc] =
                *(const float4*)(g_vproj + (size_t)(jbase + k0 + jr) * D_ + h * HD_ + dc);
        }
        __syncthreads();
#pragma unroll
        for (int kk = 0; kk < 32; kk++) {
            float a[4], b[4];
            *(float4*)&a[0] = *(const float4*)&As[kk][rm];
            *(float4*)&b[0] = *(const float4*)&Bs[kk][rn];
#pragma unroll
            for (int i = 0; i < 4; i++)
#pragma unroll
                for (int j = 0; j < 4; j++)
                    acc[i][j] += a[i] * b[j];
        }
        __syncthreads();
    }
#pragma unroll
    for (int i = 0; i < 4; i++)
#pragma unroll
        for (int j = 0; j < 4; j++)
            g_ctx_part[((size_t)sp * B_ + rm + i) * D_ + h * HD_ + rn + j] = acc[i][j];
}

__global__ void k_ctxred() {
    int i = blockIdx.x * blockDim.x + threadIdx.x;  // 32768
    float s = 0.0f;
#pragma unroll
    for (int sp = 0; sp < NSPLIT; sp++) s += g_ctx_part[(size_t)sp * B_ * D_ + i];
    g_ctx[i] = s;
}

// ---------------- launch (fork/join stream DAG, graph-capturable) ----------
extern "C" void kernel_launch(void* const* d_in, const int* in_sizes, int n_in,
                              void* d_out, int out_size) {
    const float* query  = (const float*)d_in[0];
    const float* buffer = (const float*)d_in[1];
    const float* prio   = (const float*)d_in[2];
    const float* Wq     = (const float*)d_in[3];
    const float* bq     = (const float*)d_in[4];
    const float* Wk     = (const float*)d_in[5];
    const float* bk     = (const float*)d_in[6];
    const float* Wv     = (const float*)d_in[7];
    const float* bv     = (const float*)d_in[8];
    const float* Wo     = (const float*)d_in[9];
    const float* bo     = (const float*)d_in[10];
    float* out = (float*)d_out;   // [0,32768): retrieved, [32768,163840): attn_avg

    // Lazily created ONCE on the first (uncaptured correctness) call and
    // reused forever — so all driver-side allocations happen before the
    // harness's pre-capture memory baseline and nothing is allocated during
    // capture or leaked after graph teardown. The launch sequence below is
    // identical on every call.
    static cudaStream_t s2 = nullptr, s3 = nullptr, s4 = nullptr;
    static cudaEvent_t eFork = nullptr, eQdone = nullptr, eMain = nullptr,
                       eKdone = nullptr, eVdone = nullptr, eAttn = nullptr;
    if (s2 == nullptr) {
        cudaStreamCreateWithFlags(&s2, cudaStreamNonBlocking);
        cudaStreamCreateWithFlags(&s3, cudaStreamNonBlocking);
        cudaStreamCreateWithFlags(&s4, cudaStreamNonBlocking);
        cudaEventCreateWithFlags(&eFork,  cudaEventDisableTiming);
        cudaEventCreateWithFlags(&eQdone, cudaEventDisableTiming);
        cudaEventCreateWithFlags(&eMain,  cudaEventDisableTiming);
        cudaEventCreateWithFlags(&eKdone, cudaEventDisableTiming);
        cudaEventCreateWithFlags(&eVdone, cudaEventDisableTiming);
        cudaEventCreateWithFlags(&eAttn,  cudaEventDisableTiming);
        cudaFuncSetAttribute(k_kvproj_mma, cudaFuncAttributeMaxDynamicSharedMemorySize,
                             KV_SMEM_BYTES);
    }

    // ---- fork s2: weight pre-convert + q projection (independent of selection)
    cudaEventRecord(eFork, 0);
    cudaStreamWaitEvent(s2, eFork, 0);
    k_cvtW<<<dim3(32, 32, 2), dim3(32, 8), 0, s2>>>(Wk, Wv);
    k_gemm32s<<<dim3(8, GSPLIT), 256, 0, s2>>>(query, Wq, 0);
    k_gemmred<<<128, 256, 0, s2>>>(bq, nullptr, 0);
    cudaEventRecord(eQdone, s2);

    // ---- main stream: selection chain + gather
    k_zero<<<4, 256>>>();
    k_hist_strip<<<64, 256>>>(prio);
    k_findbin<<<1, 1024>>>();
    k_compact<<<64, 256>>>(prio);
    k_selfin54<<<1, 256>>>();
    k_rank<<<K_ / 8, 256>>>();
    k_gatherA<<<K_, 256>>>(buffer);

    // join s2 (kvproj needs g_WkH/g_WvH; scores later needs g_qproj)
    cudaStreamWaitEvent(0, eQdone, 0);
    cudaEventRecord(eMain, 0);

    // K projection (main) CONCURRENT with V projection (s4)
    cudaStreamWaitEvent(s4, eMain, 0);
    k_kvproj_mma<<<dim3(8, 32), 256, KV_SMEM_BYTES, s4>>>(bv, 1);
    cudaEventRecord(eVdone, s4);

    k_kvproj_mma<<<dim3(8, 32), 256, KV_SMEM_BYTES>>>(bk, 0);
    cudaEventRecord(eKdone, 0);

    // ---- fork s3: scores -> softmax -> avg (needs kproj + qproj only)
    cudaStreamWaitEvent(s3, eKdone, 0);
    k_scores<<<dim3(32, 8), 256, 0, s3>>>();
    k_softmax<<<256, 256, 0, s3>>>();
    k_avg<<<512, 256, 0, s3>>>(out + B_ * D_);
    cudaEventRecord(eAttn, s3);

    // join s3 + s4; ctx needs attn + vproj
    cudaStreamWaitEvent(0, eAttn, 0);
    cudaStreamWaitEvent(0, eVdone, 0);
    k_ctxpart<<<dim3(8, NSPLIT), 256>>>();
    k_ctxred<<<128, 256>>>();
    k_gemm32s<<<dim3(8, GSPLIT), 256>>>(nullptr, Wo, 1);   // output projection
    k_gemmred<<<128, 256>>>(bo, out, 1);
}